// round 7
// baseline (speedup 1.0000x reference)
#include <cuda_runtime.h>
#include <cuda_bf16.h>
#include <cstdint>

// ============================================================================
// IsingRBM: psi[m] = prod_h cos(bias[h] + (x@W1)[m,h] + 0.5 * x^T W2[h] x)
// mma.sync.m16n8k16 bf16 (compute_103 baseline PTX; tcgen05 unavailable).
//
// Symmetric K-packing (upper triangle, rows 16-aligned): 164 k16-blocks in
// 41 chunks of 64 k; compile-time schedule (regions A..E).
// R7:
//  * warp grid 2M x 8N (warp tile 64x16): B-fragment duplication across
//    warps drops 4x -> 2x (R6's L1 was 41% busy, mostly duplicated LDSM).
//    1 LDSM.x4 per kb per warp (was 2).
//  * quad-barrier + 8 B-buffers kept from R6.
//  * prep kernel rewritten: one CTA per h, W2[h] staged in smem (coalesced),
//    packed bf16 emitted from smem (old version gathered W2^T from gmem).
// ============================================================================

static constexpr int kV = 64;
static constexpr int kH = 128;
static constexpr int kMTile = 128;
static constexpr int kChunks = 41;
static constexpr int kChunkBytes = kH * kV * 2;   // 16384
static constexpr int kThreads = 512;
static constexpr int kNBuf = 8;

// smem layout (bytes, relative to 1024-aligned base)
static constexpr int SM_BIAS = 0;                  // 128 f32 = 512
static constexpr int SM_PART = 512;                // 128*8 f32 = 4096
static constexpr int SM_XQ   = 4608;               // 64 j * 16 grp * 8 t u32 = 32768
static constexpr int SM_B    = 37888;              // 8 * 16384, 1024-aligned
static constexpr int SM_XT   = SM_B + 4 * kChunkBytes;      // overlay on buf 4
static constexpr int SM_END  = SM_B + kNBuf * kChunkBytes;  // 168960
static constexpr int SMEM_TOTAL = SM_END + 1024;   // 169984 < 227 KB

// Packed B operand: [chunk][h][64] bf16, cols = 4 k16-blocks per chunk.
__device__ __align__(16) __nv_bfloat16 g_wb[kChunks * kH * kV];

// ---------------------------------------------------------------------------
// helpers
// ---------------------------------------------------------------------------
__device__ __forceinline__ uint32_t smem_u32(const void* p) {
    uint32_t a;
    asm("{ .reg .u64 t; cvta.to.shared.u64 t, %1; cvt.u32.u64 %0, t; }"
        : "=r"(a) : "l"(p));
    return a;
}

#define SW128(o) ((o) ^ (((o) >> 3) & 0x70))

#define CVT_BF16X2(result, a, b) \
    asm("cvt.rn.bf16x2.f32 %0, %1, %2;" : "=r"(result) : "f"(b), "f"(a))

#define HMUL2(d, a, b) \
    asm("mul.rn.bf16x2 %0, %1, %2;" : "=r"(d) : "r"(a), "r"(b))

#define LDSM_X4(r0, r1, r2, r3, addr) \
    asm volatile("ldmatrix.sync.aligned.m8n8.x4.shared.b16 {%0,%1,%2,%3}, [%4];" \
        : "=r"(r0), "=r"(r1), "=r"(r2), "=r"(r3) : "r"(addr))

#define MMA16816(d, a0, a1, a2, a3, b0, b1) \
    asm volatile("mma.sync.aligned.m16n8k16.row.col.f32.bf16.bf16.f32 " \
        "{%0,%1,%2,%3}, {%4,%5,%6,%7}, {%8,%9}, {%0,%1,%2,%3};" \
        : "+f"((d)[0]), "+f"((d)[1]), "+f"((d)[2]), "+f"((d)[3]) \
        : "r"(a0), "r"(a1), "r"(a2), "r"(a3), "r"(b0), "r"(b1))

#define CP_ASYNC16(smem, gmem) \
    asm volatile("cp.async.cg.shared.global [%0], [%1], 16;" \
        :: "r"(smem), "l"(gmem) : "memory")
#define CP_COMMIT() asm volatile("cp.async.commit_group;" ::: "memory")
#define CP_WAIT4()  asm volatile("cp.async.wait_group 4;" ::: "memory")

__device__ __forceinline__ float cos_poly(float a) {
    // |a| < 0.1 guaranteed by problem statistics; deg-8 Taylor, err < 1e-12
    float t = a * a;
    return 1.0f + t * (-0.5f + t * (4.16666667e-2f +
               t * (-1.38888889e-3f + t * 2.48015873e-5f)));
}

// block schedule decode — used ONLY by the one-shot prep kernel
__device__ __forceinline__ int decode_i(int b) {
    if (b < 64)  return b >> 2;
    if (b < 112) return 16 + (b - 64) / 3;
    if (b < 144) return 32 + ((b - 112) >> 1);
    if (b < 160) return 48 + (b - 144);
    return 64;
}
__device__ __forceinline__ int decode_kbf(int b) {
    if (b < 64)  return b & 3;
    if (b < 112) return 1 + (b - 64) % 3;
    if (b < 144) return 2 + ((b - 112) & 1);
    if (b < 160) return 3;
    return b - 160;
}

// ---------------------------------------------------------------------------
// prep: one CTA per h. Stage W2[h] (16 KB) in smem with coalesced reads,
// then emit the packed bf16 row for every k16 block of every chunk.
// ---------------------------------------------------------------------------
__global__ void __launch_bounds__(256) prep_kernel(const float* __restrict__ w2,
                                                   const float* __restrict__ w1) {
    __shared__ float sw[4096];
    const int h = blockIdx.x;
    const float4* src = reinterpret_cast<const float4*>(w2 + (size_t)h * 4096);
    #pragma unroll
    for (int e = threadIdx.x; e < 1024; e += 256)
        reinterpret_cast<float4*>(sw)[e] = src[e];
    __syncthreads();

    // 164 blocks * 4 quads of 4 cols = 656 uint2 outputs for this h
    for (int idx = threadIdx.x; idx < 656; idx += 256) {
        int b    = idx >> 2;
        int part = idx & 3;
        int i    = decode_i(b);
        int kbf  = decode_kbf(b);
        int j0   = kbf * 16 + part * 4;
        float v[4];
        #pragma unroll
        for (int q = 0; q < 4; q++) {
            int j = j0 + q;
            if (i == 64)     v[q] = 2.0f * w1[j * kH + h];
            else if (j > i)  v[q] = sw[i * 64 + j] + sw[j * 64 + i];
            else if (j == i) v[q] = sw[i * 64 + j];
            else             v[q] = 0.0f;
        }
        uint32_t lo, hi;
        CVT_BF16X2(lo, v[0], v[1]);
        CVT_BF16X2(hi, v[2], v[3]);
        int c   = b >> 2;
        int col = (b & 3) * 16 + part * 4;
        reinterpret_cast<uint2*>(g_wb)[(c * 8192 + h * 64 + col) >> 2] =
            make_uint2(lo, hi);
    }
}

// ---------------------------------------------------------------------------
// chunk body: kbf + i-delta patterns compile-time.
// Per kb: 1 LDSM.x4 (16 N-cols x 16 k), 2 LDS.128 scale loads (8 rows),
// 16 HMUL2, 8 MMA.
// xq8: per-thread scale base; j-stride = 128 u32; entry t = row wm+g+8t.
// ---------------------------------------------------------------------------
template<int K0, int K1, int K2, int K3, int D0, int D1, int D2, int D3, bool LIN>
__device__ __forceinline__ void do_chunk(
    uint32_t bb, const uint32_t* __restrict__ boff,
    const uint32_t (&abase)[4][4][4],
    const uint32_t* __restrict__ xq8, int ibase,
    float (&acc)[4][2][4])
{
    const int KF[4] = {K0, K1, K2, K3};
    const int DI[4] = {D0, D1, D2, D3};
    #pragma unroll
    for (int kb = 0; kb < 4; kb++) {
        uint32_t sv[8];
        if (LIN) {
            #pragma unroll
            for (int t = 0; t < 8; t++) sv[t] = 0x3F803F80u;   // bf16x2(1,1)
        } else {
            const uint4* p = reinterpret_cast<const uint4*>(
                xq8 + (ibase + DI[kb]) * 128);
            uint4 s0 = p[0], s1 = p[1];
            sv[0] = s0.x; sv[1] = s0.y; sv[2] = s0.z; sv[3] = s0.w;
            sv[4] = s1.x; sv[5] = s1.y; sv[6] = s1.z; sv[7] = s1.w;
        }
        uint32_t bf[2][2];
        LDSM_X4(bf[0][0], bf[0][1], bf[1][0], bf[1][1], bb + boff[kb]);
        #pragma unroll
        for (int mb = 0; mb < 4; mb++) {
            uint32_t t0, t1, t2, t3;
            HMUL2(t0, abase[mb][KF[kb]][0], sv[2 * mb]);      // rows g,   k 0-7
            HMUL2(t1, abase[mb][KF[kb]][1], sv[2 * mb + 1]);  // rows g+8, k 0-7
            HMUL2(t2, abase[mb][KF[kb]][2], sv[2 * mb]);      // rows g,   k 8-15
            HMUL2(t3, abase[mb][KF[kb]][3], sv[2 * mb + 1]);  // rows g+8, k 8-15
            MMA16816(acc[mb][0], t0, t1, t2, t3, bf[0][0], bf[0][1]);
            MMA16816(acc[mb][1], t0, t1, t2, t3, bf[1][0], bf[1][1]);
        }
    }
}

// ---------------------------------------------------------------------------
// main fused kernel: 128-row M-tile per CTA, H=128 as N, 16 warps (2M x 8N),
// 1 CTA per SM, 8 B-buffers, barrier every 4 chunks
// ---------------------------------------------------------------------------
__global__ void __launch_bounds__(kThreads, 1)
rbm_main_kernel(const float* __restrict__ x,
                const float* __restrict__ bias,
                float* __restrict__ out) {
    extern __shared__ char smem_raw[];
    char* sm = (char*)((((uintptr_t)smem_raw) + 1023) & ~(uintptr_t)1023);
    const uint32_t sb = smem_u32(sm);
    const int tid = threadIdx.x;
    const int l   = tid & 31;
    const int w   = tid >> 5;
    const int g   = l >> 2;
    const int t4  = l & 3;
    const int wm  = (w >> 3) * 64;     // warp M offset (0,64)
    const int wn  = (w & 7) * 16;      // warp N offset (0,16,...,112)
    const int m0  = blockIdx.x * kMTile;

    float*    sbias = (float*)(sm + SM_BIAS);
    float*    spart = (float*)(sm + SM_PART);     // [m][8 wn-groups]
    uint32_t* xq    = (uint32_t*)(sm + SM_XQ);    // [j][16 grp][8 t] u32

    if (tid < kH) sbias[tid] = bias[tid];

    // --- x bf16 tile [m][j], 128B rows, SW128 swizzled (A ldmatrix source) ---
    // lives in buffer-4 space; consumed (abase LDSM) before the first quad
    // barrier, after which cp.async may overwrite it.
    {
        const float4* x4 = (const float4*)(x + (size_t)m0 * kV);
        #pragma unroll
        for (int e = tid; e < kMTile * 16; e += kThreads) {   // 128 rows * 16 float4
            int r = e >> 4, q = e & 15;
            float4 f = x4[e];
            uint32_t u0, u1;
            CVT_BF16X2(u0, f.x, f.y);
            CVT_BF16X2(u1, f.z, f.w);
            uint32_t off = (uint32_t)(r * 128 + q * 8);
            *(uint2*)(sm + SM_XT + SW128(off)) = make_uint2(u0, u1);
        }
    }
    // --- xq[j][grp][t] = bf16x2 broadcast of x[m0 + (grp>>3)*64 + (grp&7) + 8t][j]
    #pragma unroll
    for (int e = tid; e < kV * 16 * 8; e += kThreads) {   // 8192 entries
        int j   = e >> 7;
        int grp = (e >> 3) & 15;
        int t   = e & 7;
        int m   = (grp >> 3) * 64 + (grp & 7) + 8 * t;
        float v = x[(size_t)(m0 + m) * kV + j];
        uint32_t p;
        CVT_BF16X2(p, v, v);
        xq[e] = p;
    }

    // --- cp.async offsets (hoisted): 2 x 16B per thread per chunk ---
    uint32_t cp_raw[2], cp_dst[2];
    #pragma unroll
    for (int p = 0; p < 2; p++) {
        int cg = tid + p * kThreads;
        cp_raw[p] = (uint32_t)((cg >> 3) * 128 + (cg & 7) * 16);
        cp_dst[p] = SW128(cp_raw[p]);
    }
    const char* gw = (const char*)g_wb;
    #define ISSUE_CHUNK(c, buf) do {                                          \
        const char* _src = gw + (size_t)(c) * kChunkBytes;                    \
        uint32_t _dst = sb + SM_B + (uint32_t)(buf) * kChunkBytes;            \
        CP_ASYNC16(_dst + cp_dst[0], _src + cp_raw[0]);                       \
        CP_ASYNC16(_dst + cp_dst[1], _src + cp_raw[1]);                       \
    } while (0)

    // prologue: chunks 0..3 into buffers 0..3 (one group each)
    #pragma unroll
    for (int p = 0; p < 4; p++) { ISSUE_CHUNK(p, p); CP_COMMIT(); }

    __syncthreads();   // x tiles + bias ready

    // --- A-base fragments (warp's 64x64 x-tile) in registers ---
    uint32_t abase[4][4][4];
    {
        int q = l >> 3, rr = l & 7;
        #pragma unroll
        for (int mb = 0; mb < 4; mb++)
        #pragma unroll
        for (int kb = 0; kb < 4; kb++) {
            uint32_t off = (uint32_t)((wm + 16 * mb + (q & 1) * 8 + rr) * 128
                                      + (kb * 16 + (q >> 1) * 8) * 2);
            LDSM_X4(abase[mb][kb][0], abase[mb][kb][1],
                    abase[mb][kb][2], abase[mb][kb][3],
                    sb + SM_XT + SW128(off));
        }
    }

    // --- per-thread B ldmatrix offsets: one LDSM.x4 per kb (16 cols x 16 k) ---
    uint32_t boff[4];
    {
        int q = l >> 3, rr = l & 7;
        #pragma unroll
        for (int kb = 0; kb < 4; kb++) {
            uint32_t off = (uint32_t)((wn + (q >> 1) * 8 + rr) * 128
                                      + (kb * 16 + (q & 1) * 8) * 2);
            boff[kb] = SW128(off);
        }
    }

    float acc[4][2][4];
    #pragma unroll
    for (int a = 0; a < 4; a++)
    #pragma unroll
    for (int b = 0; b < 2; b++)
    #pragma unroll
    for (int c = 0; c < 4; c++) acc[a][b][c] = 0.0f;

    const uint32_t* xq8 = xq + ((w >> 3) * 8 + g) * 8;   // grp stride 8

    // quad pipeline step: every 4th chunk: barrier (buffers of chunks c-4..c-1
    // now reusable by ALL warps) -> issue chunks c+4..c+7 (exactly 4 commits)
    // -> wait_group 4 (chunks c..c+3 landed).
    int c = 0;
    #define PIPE(BODY) do {                                                   \
        if ((c & 3) == 0) {                                                   \
            __syncthreads();                                                  \
            _Pragma("unroll")                                                 \
            for (int _q = 0; _q < 4; _q++) {                                  \
                if (c + 4 + _q < kChunks)                                     \
                    ISSUE_CHUNK(c + 4 + _q, (c + 4 + _q) & 7);                \
                CP_COMMIT();                                                  \
            }                                                                 \
            CP_WAIT4();                                                       \
        }                                                                     \
        uint32_t bb = sb + SM_B + (uint32_t)(c & 7) * kChunkBytes;            \
        BODY;                                                                 \
        c++;                                                                  \
    } while (0)

    // Region A: i = c, kbf 0..3
    #pragma unroll 1
    for (int cc = 0; cc < 16; cc++) {
        PIPE((do_chunk<0,1,2,3, 0,0,0,0, false>(bb, boff, abase, xq8, cc, acc)));
    }
    // Region B: 3-chunk period, i 16..31
    int I = 16;
    #pragma unroll 1
    for (int r = 0; r < 4; r++) {
        PIPE((do_chunk<1,2,3,1, 0,0,0,1, false>(bb, boff, abase, xq8, I,     acc)));
        PIPE((do_chunk<2,3,1,2, 0,0,1,1, false>(bb, boff, abase, xq8, I + 1, acc)));
        PIPE((do_chunk<3,1,2,3, 0,1,1,1, false>(bb, boff, abase, xq8, I + 2, acc)));
        I += 4;
    }
    // Region C: i 32..47
    #pragma unroll 1
    for (int r = 0; r < 8; r++) {
        PIPE((do_chunk<2,3,2,3, 0,0,1,1, false>(bb, boff, abase, xq8, I, acc)));
        I += 2;
    }
    // Region D: i 48..63
    #pragma unroll 1
    for (int r = 0; r < 4; r++) {
        PIPE((do_chunk<3,3,3,3, 0,1,2,3, false>(bb, boff, abase, xq8, I, acc)));
        I += 4;
    }
    // Region E: linear term (chunk 40 — quad step fires: c & 3 == 0)
    PIPE((do_chunk<0,1,2,3, 0,0,0,0, true>(bb, boff, abase, xq8, 0, acc)));

    // --- epilogue: a = bias + 0.5*acc; psi = prod cos(a) ---
    #pragma unroll
    for (int mb = 0; mb < 4; mb++) {
        float p0 = 1.0f, p1 = 1.0f;
        #pragma unroll
        for (int nb = 0; nb < 2; nb++) {
            int col = wn + nb * 8 + 2 * t4;
            #pragma unroll
            for (int cc = 0; cc < 2; cc++) {
                float bv = sbias[col + cc];
                p0 *= cos_poly(bv + 0.5f * acc[mb][nb][cc]);       // row g
                p1 *= cos_poly(bv + 0.5f * acc[mb][nb][2 + cc]);   // row g+8
            }
        }
        // reduce over the quad (t4 = 0..3) -> product over warp's 16 cols
        p0 *= __shfl_xor_sync(0xFFFFFFFFu, p0, 1);
        p0 *= __shfl_xor_sync(0xFFFFFFFFu, p0, 2);
        p1 *= __shfl_xor_sync(0xFFFFFFFFu, p1, 1);
        p1 *= __shfl_xor_sync(0xFFFFFFFFu, p1, 2);
        if (t4 == 0) {
            int r0 = wm + 16 * mb + g;
            spart[r0 * 8 + (w & 7)]       = p0;
            spart[(r0 + 8) * 8 + (w & 7)] = p1;
        }
    }
    __syncthreads();
    if (tid < kMTile) {
        const float* sp = spart + tid * 8;
        float pr = ((sp[0] * sp[1]) * (sp[2] * sp[3]))
                 * ((sp[4] * sp[5]) * (sp[6] * sp[7]));
        out[m0 + tid] = pr;
    }
}

// ---------------------------------------------------------------------------
// launch
// ---------------------------------------------------------------------------
extern "C" void kernel_launch(void* const* d_in, const int* in_sizes, int n_in,
                              void* d_out, int out_size) {
    const float* x    = (const float*)d_in[0];   // (16384, 64)
    const float* w1   = (const float*)d_in[1];   // (64, 128)
    const float* w2   = (const float*)d_in[2];   // (128, 64, 64)
    const float* bias = (const float*)d_in[3];   // (128,)
    float* out = (float*)d_out;                  // (16384,)

    cudaFuncSetAttribute(rbm_main_kernel,
                         cudaFuncAttributeMaxDynamicSharedMemorySize, SMEM_TOTAL);

    prep_kernel<<<kH, 256>>>(w2, w1);            // one CTA per h
    rbm_main_kernel<<<16384 / kMTile, kThreads, SMEM_TOTAL>>>(x, bias, out);
}

// round 8
// speedup vs baseline: 1.0662x; 1.0662x over previous
#include <cuda_runtime.h>
#include <cuda_bf16.h>
#include <cstdint>

// ============================================================================
// IsingRBM: psi[m] = prod_h cos(bias[h] + (x@W1)[m,h] + 0.5 * x^T W2[h] x)
// mma.sync.m16n8k16 bf16 (compute_103 baseline PTX; tcgen05 unavailable).
//
// Symmetric K-packing (upper triangle, rows 16-aligned): 164 k16-blocks in
// 41 chunks of 64 k; compile-time schedule (regions A..E).
// R8 = best pieces of R4/R6/R7:
//  * 2 CTAs x 256 threads per SM (M-tile 64, warp grid 2M x 4N) — two
//    independent barrier domains interleave (R4), regs stay ~128 with
//    fma ~13% (unlike R7's 2Mx8N).
//  * pair-barriers: __syncthreads every 2 chunks (21 total vs R4's 41),
//    4 B-buffers, issue chunks c+2,c+3 post-barrier, cp.async.wait_group 2.
//  * R7's fast prep (one CTA per h, W2[h] staged in smem).
// ============================================================================

static constexpr int kV = 64;
static constexpr int kH = 128;
static constexpr int kMTile = 64;
static constexpr int kChunks = 41;
static constexpr int kChunkBytes = kH * kV * 2;   // 16384
static constexpr int kThreads = 256;

// smem layout (bytes, relative to 1024-aligned base)
static constexpr int SM_BIAS = 0;                  // 128 f32 = 512
static constexpr int SM_PART = 512;                // 64*4 f32 = 1024
static constexpr int SM_XQ   = 1536;               // 64 j * 16 grp * 4 t u32 = 16384
static constexpr int SM_B    = 18432;              // 4 * 16384 (1024-aligned)
static constexpr int SM_XT   = SM_B + 2 * kChunkBytes;  // overlay on buffer 2
static constexpr int SM_END  = SM_B + 4 * kChunkBytes;  // 83968
static constexpr int SMEM_TOTAL = SM_END + 1024;   // 84992; x2 CTAs = 169984 < 227K

// Packed B operand: [chunk][h][64] bf16, cols = 4 k16-blocks per chunk.
__device__ __align__(16) __nv_bfloat16 g_wb[kChunks * kH * kV];

// ---------------------------------------------------------------------------
// helpers
// ---------------------------------------------------------------------------
__device__ __forceinline__ uint32_t smem_u32(const void* p) {
    uint32_t a;
    asm("{ .reg .u64 t; cvta.to.shared.u64 t, %1; cvt.u32.u64 %0, t; }"
        : "=r"(a) : "l"(p));
    return a;
}

#define SW128(o) ((o) ^ (((o) >> 3) & 0x70))

#define CVT_BF16X2(result, a, b) \
    asm("cvt.rn.bf16x2.f32 %0, %1, %2;" : "=r"(result) : "f"(b), "f"(a))

#define HMUL2(d, a, b) \
    asm("mul.rn.bf16x2 %0, %1, %2;" : "=r"(d) : "r"(a), "r"(b))

#define LDSM_X4(r0, r1, r2, r3, addr) \
    asm volatile("ldmatrix.sync.aligned.m8n8.x4.shared.b16 {%0,%1,%2,%3}, [%4];" \
        : "=r"(r0), "=r"(r1), "=r"(r2), "=r"(r3) : "r"(addr))

#define MMA16816(d, a0, a1, a2, a3, b0, b1) \
    asm volatile("mma.sync.aligned.m16n8k16.row.col.f32.bf16.bf16.f32 " \
        "{%0,%1,%2,%3}, {%4,%5,%6,%7}, {%8,%9}, {%0,%1,%2,%3};" \
        : "+f"((d)[0]), "+f"((d)[1]), "+f"((d)[2]), "+f"((d)[3]) \
        : "r"(a0), "r"(a1), "r"(a2), "r"(a3), "r"(b0), "r"(b1))

#define CP_ASYNC16(smem, gmem) \
    asm volatile("cp.async.cg.shared.global [%0], [%1], 16;" \
        :: "r"(smem), "l"(gmem) : "memory")
#define CP_COMMIT() asm volatile("cp.async.commit_group;" ::: "memory")
#define CP_WAIT2()  asm volatile("cp.async.wait_group 2;" ::: "memory")

__device__ __forceinline__ float cos_poly(float a) {
    // |a| < 0.1 guaranteed by problem statistics; deg-8 Taylor, err < 1e-12
    float t = a * a;
    return 1.0f + t * (-0.5f + t * (4.16666667e-2f +
               t * (-1.38888889e-3f + t * 2.48015873e-5f)));
}

// block schedule decode — used ONLY by the one-shot prep kernel
__device__ __forceinline__ int decode_i(int b) {
    if (b < 64)  return b >> 2;
    if (b < 112) return 16 + (b - 64) / 3;
    if (b < 144) return 32 + ((b - 112) >> 1);
    if (b < 160) return 48 + (b - 144);
    return 64;
}
__device__ __forceinline__ int decode_kbf(int b) {
    if (b < 64)  return b & 3;
    if (b < 112) return 1 + (b - 64) % 3;
    if (b < 144) return 2 + ((b - 112) & 1);
    if (b < 160) return 3;
    return b - 160;
}

// ---------------------------------------------------------------------------
// prep (R7): one CTA per h. Stage W2[h] (16 KB) in smem with coalesced reads,
// then emit the packed bf16 row for every k16 block of every chunk.
// ---------------------------------------------------------------------------
__global__ void __launch_bounds__(256) prep_kernel(const float* __restrict__ w2,
                                                   const float* __restrict__ w1) {
    __shared__ float sw[4096];
    const int h = blockIdx.x;
    const float4* src = reinterpret_cast<const float4*>(w2 + (size_t)h * 4096);
    #pragma unroll
    for (int e = threadIdx.x; e < 1024; e += 256)
        reinterpret_cast<float4*>(sw)[e] = src[e];
    __syncthreads();

    // 164 blocks * 4 quads of 4 cols = 656 uint2 outputs for this h
    for (int idx = threadIdx.x; idx < 656; idx += 256) {
        int b    = idx >> 2;
        int part = idx & 3;
        int i    = decode_i(b);
        int kbf  = decode_kbf(b);
        int j0   = kbf * 16 + part * 4;
        float v[4];
        #pragma unroll
        for (int q = 0; q < 4; q++) {
            int j = j0 + q;
            if (i == 64)     v[q] = 2.0f * w1[j * kH + h];
            else if (j > i)  v[q] = sw[i * 64 + j] + sw[j * 64 + i];
            else if (j == i) v[q] = sw[i * 64 + j];
            else             v[q] = 0.0f;
        }
        uint32_t lo, hi;
        CVT_BF16X2(lo, v[0], v[1]);
        CVT_BF16X2(hi, v[2], v[3]);
        int c   = b >> 2;
        int col = (b & 3) * 16 + part * 4;
        reinterpret_cast<uint2*>(g_wb)[(c * 8192 + h * 64 + col) >> 2] =
            make_uint2(lo, hi);
    }
}

// ---------------------------------------------------------------------------
// chunk body (R4 structure): kbf + i-delta patterns compile-time.
// xq4: per-thread scale base; one LDS.128 per kb yields 4 broadcast scales
// for rows wm+g+{0,8,16,24}; j-stride = 64 u32.
// ---------------------------------------------------------------------------
template<int K0, int K1, int K2, int K3, int D0, int D1, int D2, int D3, bool LIN>
__device__ __forceinline__ void do_chunk(
    uint32_t bb, const uint32_t* __restrict__ boff,
    const uint32_t (&abase)[2][4][4],
    const uint32_t* __restrict__ xq4, int ibase,
    float (&acc)[2][4][4])
{
    const int KF[4] = {K0, K1, K2, K3};
    const int DI[4] = {D0, D1, D2, D3};
    #pragma unroll
    for (int kb = 0; kb < 4; kb++) {
        uint32_t sv[4];
        if (LIN) {
            sv[0] = sv[1] = sv[2] = sv[3] = 0x3F803F80u;   // bf16x2(1,1)
        } else {
            uint4 s = *reinterpret_cast<const uint4*>(
                xq4 + (ibase + DI[kb]) * 64);
            sv[0] = s.x; sv[1] = s.y; sv[2] = s.z; sv[3] = s.w;
        }
        uint32_t bf[4][2];
        LDSM_X4(bf[0][0], bf[0][1], bf[1][0], bf[1][1], bb + boff[kb * 2 + 0]);
        LDSM_X4(bf[2][0], bf[2][1], bf[3][0], bf[3][1], bb + boff[kb * 2 + 1]);
        #pragma unroll
        for (int mb = 0; mb < 2; mb++) {
            uint32_t t0, t1, t2, t3;
            HMUL2(t0, abase[mb][KF[kb]][0], sv[2 * mb]);      // rows g
            HMUL2(t1, abase[mb][KF[kb]][1], sv[2 * mb + 1]);  // rows g+8
            HMUL2(t2, abase[mb][KF[kb]][2], sv[2 * mb]);
            HMUL2(t3, abase[mb][KF[kb]][3], sv[2 * mb + 1]);
            #pragma unroll
            for (int nb = 0; nb < 4; nb++)
                MMA16816(acc[mb][nb], t0, t1, t2, t3, bf[nb][0], bf[nb][1]);
        }
    }
}

// ---------------------------------------------------------------------------
// main fused kernel: 64-row M-tile per CTA, H=128 as N, 8 warps (2M x 4N),
// 2 CTAs per SM, 4 B-buffers, barrier every 2 chunks
// ---------------------------------------------------------------------------
__global__ void __launch_bounds__(kThreads, 2)
rbm_main_kernel(const float* __restrict__ x,
                const float* __restrict__ bias,
                float* __restrict__ out) {
    extern __shared__ char smem_raw[];
    char* sm = (char*)((((uintptr_t)smem_raw) + 1023) & ~(uintptr_t)1023);
    const uint32_t sb = smem_u32(sm);
    const int tid = threadIdx.x;
    const int l   = tid & 31;
    const int w   = tid >> 5;
    const int g   = l >> 2;
    const int t4  = l & 3;
    const int wm  = (w >> 2) * 32;     // warp M offset (0,32)
    const int wn  = (w & 3) * 32;      // warp N offset (0,32,64,96)
    const int m0  = blockIdx.x * kMTile;

    float*    sbias = (float*)(sm + SM_BIAS);
    float*    spart = (float*)(sm + SM_PART);     // [m][4 wn-groups]
    uint32_t* xq    = (uint32_t*)(sm + SM_XQ);    // [j][16 grp][4 t] u32

    if (tid < kH) sbias[tid] = bias[tid];

    // --- x bf16 tile [m][j], 128B rows, SW128 swizzled (A ldmatrix source) ---
    // lives in buffer-2 space; consumed (abase LDSM) before the first pair
    // barrier, after which cp.async may overwrite it.
    {
        const float4* x4 = (const float4*)(x + (size_t)m0 * kV);
        #pragma unroll
        for (int e = tid; e < kMTile * 16; e += kThreads) {   // 64 rows * 16 float4
            int r = e >> 4, q = e & 15;
            float4 f = x4[e];
            uint32_t u0, u1;
            CVT_BF16X2(u0, f.x, f.y);
            CVT_BF16X2(u1, f.z, f.w);
            uint32_t off = (uint32_t)(r * 128 + q * 8);
            *(uint2*)(sm + SM_XT + SW128(off)) = make_uint2(u0, u1);
        }
    }
    // --- xq[j][grp][t] = bf16x2 broadcast of x[m0 + (grp>>3)*32 + (grp&7) + 8t][j]
    #pragma unroll
    for (int e = tid; e < kV * 16 * 4; e += kThreads) {   // 4096 entries
        int j   = e >> 6;
        int grp = (e >> 2) & 15;
        int t   = e & 3;
        int m   = (grp >> 3) * 32 + (grp & 7) + 8 * t;
        float v = x[(size_t)(m0 + m) * kV + j];
        uint32_t p;
        CVT_BF16X2(p, v, v);
        xq[e] = p;
    }

    // --- cp.async offsets (hoisted): 4 x 16B per thread per chunk ---
    uint32_t cp_raw[4], cp_dst[4];
    #pragma unroll
    for (int p = 0; p < 4; p++) {
        int cg = tid + p * kThreads;
        cp_raw[p] = (uint32_t)((cg >> 3) * 128 + (cg & 7) * 16);
        cp_dst[p] = SW128(cp_raw[p]);
    }
    const char* gw = (const char*)g_wb;
    #define ISSUE_CHUNK(c, buf) do {                                          \
        const char* _src = gw + (size_t)(c) * kChunkBytes;                    \
        uint32_t _dst = sb + SM_B + (uint32_t)(buf) * kChunkBytes;            \
        _Pragma("unroll")                                                     \
        for (int _p = 0; _p < 4; _p++)                                        \
            CP_ASYNC16(_dst + cp_dst[_p], _src + cp_raw[_p]);                 \
    } while (0)

    // prologue: chunks 0,1 into buffers 0,1 (one commit each)
    ISSUE_CHUNK(0, 0); CP_COMMIT();
    ISSUE_CHUNK(1, 1); CP_COMMIT();

    __syncthreads();   // x tiles + bias ready

    // --- A-base fragments (warp's 32x64 x-tile) in registers ---
    uint32_t abase[2][4][4];
    {
        int q = l >> 3, rr = l & 7;
        #pragma unroll
        for (int mb = 0; mb < 2; mb++)
        #pragma unroll
        for (int kb = 0; kb < 4; kb++) {
            uint32_t off = (uint32_t)((wm + 16 * mb + (q & 1) * 8 + rr) * 128
                                      + (kb * 16 + (q >> 1) * 8) * 2);
            LDSM_X4(abase[mb][kb][0], abase[mb][kb][1],
                    abase[mb][kb][2], abase[mb][kb][3],
                    sb + SM_XT + SW128(off));
        }
    }

    // --- per-thread B ldmatrix offsets (swizzled, rel. to buffer base) ---
    uint32_t boff[8];
    {
        int q = l >> 3, rr = l & 7;
        #pragma unroll
        for (int kb = 0; kb < 4; kb++)
        #pragma unroll
        for (int nb2 = 0; nb2 < 2; nb2++) {
            uint32_t off = (uint32_t)((wn + nb2 * 16 + (q >> 1) * 8 + rr) * 128
                                      + (kb * 16 + (q & 1) * 8) * 2);
            boff[kb * 2 + nb2] = SW128(off);
        }
    }

    float acc[2][4][4];
    #pragma unroll
    for (int a = 0; a < 2; a++)
    #pragma unroll
    for (int b = 0; b < 4; b++)
    #pragma unroll
    for (int c = 0; c < 4; c++) acc[a][b][c] = 0.0f;

    const int rb0 = wm + g;
    const uint32_t* xq4 = xq + ((wm >> 2) + g) * 4;   // grp = (wm>>2)+g

    // pair pipeline: at even c: barrier (buffers of chunks c-2,c-1 reusable
    // by ALL warps) -> issue chunks c+2,c+3 (always 2 commits) ->
    // wait_group 2 (chunks c,c+1 landed).
    int c = 0;
    #define PIPE(BODY) do {                                                   \
        if ((c & 1) == 0) {                                                   \
            __syncthreads();                                                  \
            if (c + 2 < kChunks) ISSUE_CHUNK(c + 2, (c + 2) & 3);             \
            CP_COMMIT();                                                      \
            if (c + 3 < kChunks) ISSUE_CHUNK(c + 3, (c + 3) & 3);             \
            CP_COMMIT();                                                      \
            CP_WAIT2();                                                       \
        }                                                                     \
        uint32_t bb = sb + SM_B + (uint32_t)(c & 3) * kChunkBytes;            \
        BODY;                                                                 \
        c++;                                                                  \
    } while (0)

    // Region A: i = c, kbf 0..3
    #pragma unroll 1
    for (int cc = 0; cc < 16; cc++) {
        PIPE((do_chunk<0,1,2,3, 0,0,0,0, false>(bb, boff, abase, xq4, cc, acc)));
    }
    // Region B: 3-chunk period, i 16..31
    int I = 16;
    #pragma unroll 1
    for (int r = 0; r < 4; r++) {
        PIPE((do_chunk<1,2,3,1, 0,0,0,1, false>(bb, boff, abase, xq4, I,     acc)));
        PIPE((do_chunk<2,3,1,2, 0,0,1,1, false>(bb, boff, abase, xq4, I + 1, acc)));
        PIPE((do_chunk<3,1,2,3, 0,1,1,1, false>(bb, boff, abase, xq4, I + 2, acc)));
        I += 4;
    }
    // Region C: i 32..47
    #pragma unroll 1
    for (int r = 0; r < 8; r++) {
        PIPE((do_chunk<2,3,2,3, 0,0,1,1, false>(bb, boff, abase, xq4, I, acc)));
        I += 2;
    }
    // Region D: i 48..63
    #pragma unroll 1
    for (int r = 0; r < 4; r++) {
        PIPE((do_chunk<3,3,3,3, 0,1,2,3, false>(bb, boff, abase, xq4, I, acc)));
        I += 4;
    }
    // Region E: linear term (chunk 40, even -> pair step fires)
    PIPE((do_chunk<0,1,2,3, 0,0,0,0, true>(bb, boff, abase, xq4, 0, acc)));

    // --- epilogue: a = bias + 0.5*acc; psi = prod cos(a) ---
    #pragma unroll
    for (int mb = 0; mb < 2; mb++) {
        float p0 = 1.0f, p1 = 1.0f;
        #pragma unroll
        for (int nb = 0; nb < 4; nb++) {
            int col = wn + nb * 8 + 2 * t4;
            #pragma unroll
            for (int cc = 0; cc < 2; cc++) {
                float bv = sbias[col + cc];
                p0 *= cos_poly(bv + 0.5f * acc[mb][nb][cc]);       // row g
                p1 *= cos_poly(bv + 0.5f * acc[mb][nb][2 + cc]);   // row g+8
            }
        }
        p0 *= __shfl_xor_sync(0xFFFFFFFFu, p0, 1);
        p0 *= __shfl_xor_sync(0xFFFFFFFFu, p0, 2);
        p1 *= __shfl_xor_sync(0xFFFFFFFFu, p1, 1);
        p1 *= __shfl_xor_sync(0xFFFFFFFFu, p1, 2);
        if (t4 == 0) {
            spart[(rb0 + 16 * mb) * 4 + (w & 3)]     = p0;
            spart[(rb0 + 16 * mb + 8) * 4 + (w & 3)] = p1;
        }
    }
    __syncthreads();
    if (tid < kMTile) {
        out[m0 + tid] = spart[tid * 4 + 0] * spart[tid * 4 + 1]
                      * spart[tid * 4 + 2] * spart[tid * 4 + 3];
    }
}

// ---------------------------------------------------------------------------
// launch
// ---------------------------------------------------------------------------
extern "C" void kernel_launch(void* const* d_in, const int* in_sizes, int n_in,
                              void* d_out, int out_size) {
    const float* x    = (const float*)d_in[0];   // (16384, 64)
    const float* w1   = (const float*)d_in[1];   // (64, 128)
    const float* w2   = (const float*)d_in[2];   // (128, 64, 64)
    const float* bias = (const float*)d_in[3];   // (128,)
    float* out = (float*)d_out;                  // (16384,)

    cudaFuncSetAttribute(rbm_main_kernel,
                         cudaFuncAttributeMaxDynamicSharedMemorySize, SMEM_TOTAL);

    prep_kernel<<<kH, 256>>>(w2, w1);            // one CTA per h
    rbm_main_kernel<<<16384 / kMTile, kThreads, SMEM_TOTAL>>>(x, bias, out);
}